// round 3
// baseline (speedup 1.0000x reference)
#include <cuda_runtime.h>

// Dims (hardcoded from reference): B=64, T=64, D=32, H=128, W=256, L=64, K_SUB=2

// ---------------- device scratch: repacked weights (float4 along K, row-major in out-dim) ----
// w0:  (256,129) -> g_w0q[k4][j], k4<33 (pad K 129->132)
// w1:  (256,256) -> g_w1q[k4][j], k4<64
// w2:  (128,256) -> g_w2q[k4][row], k4<64
// wih: (384,33)  -> g_wihq[k4][row], k4<9 (pad 33->36)
// whh: (384,128) -> g_whhq[k4][row], k4<32
__device__ float4 g_w0q [33 * 256];
__device__ float4 g_w1q [64 * 256];
__device__ float4 g_w2q [64 * 128];
__device__ float4 g_wihq[ 9 * 384];
__device__ float4 g_whhq[32 * 384];

__global__ void prep_kernel(const float* __restrict__ w0, const float* __restrict__ w1,
                            const float* __restrict__ w2, const float* __restrict__ wih,
                            const float* __restrict__ whh)
{
    int i0 = blockIdx.x * blockDim.x + threadIdx.x;
    int stride = gridDim.x * blockDim.x;

    for (int idx = i0; idx < 33 * 256; idx += stride) {
        int k4 = idx >> 8, j = idx & 255, k = 4 * k4;
        float4 v;
        v.x = (k + 0 < 129) ? w0[j * 129 + k + 0] : 0.f;
        v.y = (k + 1 < 129) ? w0[j * 129 + k + 1] : 0.f;
        v.z = (k + 2 < 129) ? w0[j * 129 + k + 2] : 0.f;
        v.w = (k + 3 < 129) ? w0[j * 129 + k + 3] : 0.f;
        g_w0q[idx] = v;
    }
    for (int idx = i0; idx < 64 * 256; idx += stride) {
        int k4 = idx >> 8, j = idx & 255, k = 4 * k4;
        g_w1q[idx] = make_float4(w1[j * 256 + k], w1[j * 256 + k + 1],
                                 w1[j * 256 + k + 2], w1[j * 256 + k + 3]);
    }
    for (int idx = i0; idx < 64 * 128; idx += stride) {
        int k4 = idx >> 7, j = idx & 127, k = 4 * k4;
        g_w2q[idx] = make_float4(w2[j * 256 + k], w2[j * 256 + k + 1],
                                 w2[j * 256 + k + 2], w2[j * 256 + k + 3]);
    }
    for (int idx = i0; idx < 9 * 384; idx += stride) {
        int k4 = idx / 384, j = idx % 384, k = 4 * k4;
        float4 v;
        v.x = (k + 0 < 33) ? wih[j * 33 + k + 0] : 0.f;
        v.y = (k + 1 < 33) ? wih[j * 33 + k + 1] : 0.f;
        v.z = (k + 2 < 33) ? wih[j * 33 + k + 2] : 0.f;
        v.w = (k + 3 < 33) ? wih[j * 33 + k + 3] : 0.f;
        g_wihq[idx] = v;
    }
    for (int idx = i0; idx < 32 * 384; idx += stride) {
        int k4 = idx / 384, j = idx % 384, k = 4 * k4;
        g_whhq[idx] = make_float4(whh[j * 128 + k], whh[j * 128 + k + 1],
                                  whh[j * 128 + k + 2], whh[j * 128 + k + 3]);
    }
}

__device__ __forceinline__ float softplusf(float x) {
    return fmaxf(x, 0.f) + log1pf(expf(-fabsf(x)));
}
__device__ __forceinline__ float sigmoidf(float x) {
    return 1.f / (1.f + expf(-x));
}

__global__ void __launch_bounds__(256, 1)
solve_kernel(const float* __restrict__ ts, const float* __restrict__ ys,
             const float* __restrict__ scale,
             const float* __restrict__ mlp_b0, const float* __restrict__ mlp_b1,
             const float* __restrict__ mlp_b2,
             const float* __restrict__ gru_b, const float* __restrict__ gru_bn,
             const float* __restrict__ htl_w, const float* __restrict__ htl_b,
             const float* __restrict__ htb_w, const float* __restrict__ htb_b,
             const float* __restrict__ lti_w, const float* __restrict__ lti_b,
             const float* __restrict__ lth_w, const float* __restrict__ lth_b,
             float* __restrict__ out)
{
    const int b = blockIdx.x;
    const int tid = threadIdx.x;

    __shared__ __align__(16) float s_xg[36];       // GRU input [t, y(32)] padded
    __shared__ __align__(16) float s_hid[128];
    __shared__ float s_ih[384], s_hh[384];
    __shared__ __align__(16) float s_y[136];       // state: [SEIAR(5), h(128)]
    __shared__ __align__(16) float s_tmp[136];
    __shared__ float s_k[6][133];
    __shared__ __align__(16) float s_xv[132];      // mlp input [t, h(128)] padded
    __shared__ __align__(16) float s_a0[256];
    __shared__ __align__(16) float s_a1[256];
    __shared__ float s_part[256];
    __shared__ float s_z0[64];
    __shared__ float s_beta;

    // output layout: traj[:, :5] (B,T,5) || traj[:, 5:] (B,T,128) || z0 (B,64)
    const int OFF_H = 64 * 64 * 5;
    const int OFF_Z = OFF_H + 64 * 64 * 128;

    if (tid < 128) s_hid[tid] = 0.f;
    if (tid >= 33 && tid < 36) s_xg[tid] = 0.f;
    if (tid >= 129 && tid < 132) s_xv[tid] = 0.f;
    __syncthreads();

    // ---------------- GRU over reversed sequence ----------------
    for (int step = 0; step < 64; ++step) {
        int r = 63 - step;
        if (tid == 0) s_xg[0] = ts[b * 64 + r];
        if (tid >= 1 && tid < 33) s_xg[tid] = ys[(b * 64 + r) * 32 + (tid - 1)];
        __syncthreads();

        const float4* xg4 = (const float4*)s_xg;
        const float4* h4  = (const float4*)s_hid;
        for (int row = tid; row < 384; row += 256) {
            float a0 = gru_b[row], a1 = 0.f;
            #pragma unroll
            for (int k = 0; k < 9; ++k) {
                float4 w = g_wihq[k * 384 + row];
                float4 x = xg4[k];
                a0 = fmaf(w.x, x.x, fmaf(w.z, x.z, a0));
                a1 = fmaf(w.y, x.y, fmaf(w.w, x.w, a1));
            }
            float b0 = 0.f, b1 = 0.f;
            #pragma unroll 8
            for (int k = 0; k < 32; ++k) {
                float4 w = g_whhq[k * 384 + row];
                float4 x = h4[k];
                b0 = fmaf(w.x, x.x, fmaf(w.z, x.z, b0));
                b1 = fmaf(w.y, x.y, fmaf(w.w, x.w, b1));
            }
            s_ih[row] = a0 + a1;
            s_hh[row] = b0 + b1;
        }
        __syncthreads();
        if (tid < 128) {
            float rr = sigmoidf(s_ih[tid] + s_hh[tid]);
            float zz = sigmoidf(s_ih[128 + tid] + s_hh[128 + tid]);
            float nn = tanhf(s_ih[256 + tid] + rr * (s_hh[256 + tid] + gru_bn[tid]));
            s_hid[tid] = nn + zz * (s_hid[tid] - nn);
        }
        __syncthreads();
    }

    // ---------------- head: z0, h0, y0 ----------------
    if (tid < 64) {
        float acc = htl_b[tid];
        #pragma unroll 8
        for (int k = 0; k < 128; ++k) acc = fmaf(htl_w[tid * 128 + k], s_hid[k], acc);
        s_z0[tid] = acc;
        out[OFF_Z + b * 64 + tid] = acc;
    }
    __syncthreads();
    if (tid < 128) {
        float acc = lth_b[tid];
        #pragma unroll 8
        for (int k = 0; k < 64; ++k) acc = fmaf(lth_w[tid * 64 + k], s_z0[k], acc);
        s_y[5 + tid] = acc;
    }
    if (tid == 0) {
        float lg[5], mx = -1e30f;
        #pragma unroll
        for (int m = 0; m < 5; ++m) {
            float acc = lti_b[m];
            for (int k = 0; k < 64; ++k) acc = fmaf(lti_w[m * 64 + k], s_z0[k], acc);
            lg[m] = acc;
            mx = fmaxf(mx, acc);
        }
        float sum = 0.f;
        #pragma unroll
        for (int m = 0; m < 5; ++m) { float e = expf(lg[m] - mx); s_y[m] = e; sum += e; }
        #pragma unroll
        for (int m = 0; m < 5; ++m) s_y[m] /= sum;
    }
    __syncthreads();

    // ---------------- ODE solve ----------------
    const float scl   = scale[0];
    const float bias0 = mlp_b0[tid];
    const float bias1 = mlp_b1[tid];
    const float bias2 = (tid < 128) ? mlp_b2[tid] : 0.f;
    const float htbb  = htb_b[0];

    // vf: kout = f(t, yv); yv/kout are smem arrays of length 133
    auto vf = [&](float tt, const float* yv, float* kout) {
        if (tid == 0) s_xv[0] = tt;
        if (tid < 128) s_xv[1 + tid] = yv[5 + tid];
        if (tid < 32) {
            float p = fmaf(htb_w[tid], yv[5 + tid],
                      fmaf(htb_w[tid + 32], yv[37 + tid],
                      fmaf(htb_w[tid + 64], yv[69 + tid],
                           htb_w[tid + 96] * yv[101 + tid])));
            #pragma unroll
            for (int o = 16; o > 0; o >>= 1) p += __shfl_xor_sync(0xffffffffu, p, o);
            if (tid == 0) s_beta = sigmoidf(0.01f * (p + htbb));
        }
        __syncthreads();

        // layer 0: W0(256x129) @ xv
        {
            const float4* xv4 = (const float4*)s_xv;
            float a0 = bias0, a1 = 0.f;
            #pragma unroll
            for (int k = 0; k < 33; ++k) {
                float4 w = g_w0q[k * 256 + tid];
                float4 x = xv4[k];
                a0 = fmaf(w.x, x.x, fmaf(w.z, x.z, a0));
                a1 = fmaf(w.y, x.y, fmaf(w.w, x.w, a1));
            }
            s_a0[tid] = softplusf(a0 + a1);
        }
        __syncthreads();

        // layer 1: W1(256x256) @ a0
        {
            const float4* a04 = (const float4*)s_a0;
            float a0 = bias1, a1 = 0.f;
            #pragma unroll 8
            for (int k = 0; k < 64; ++k) {
                float4 w = g_w1q[k * 256 + tid];
                float4 x = a04[k];
                a0 = fmaf(w.x, x.x, fmaf(w.z, x.z, a0));
                a1 = fmaf(w.y, x.y, fmaf(w.w, x.w, a1));
            }
            s_a1[tid] = softplusf(a0 + a1);
        }
        __syncthreads();

        // layer 2: W2(128x256) @ a1, split K across two thread halves
        {
            const float4* a14 = (const float4*)s_a1;
            int row = tid & 127, half = tid >> 7;
            float a0 = 0.f, a1 = 0.f;
            int kb = half * 32;
            #pragma unroll 8
            for (int k = kb; k < kb + 32; ++k) {
                float4 w = g_w2q[k * 128 + row];
                float4 x = a14[k];
                a0 = fmaf(w.x, x.x, fmaf(w.z, x.z, a0));
                a1 = fmaf(w.y, x.y, fmaf(w.w, x.w, a1));
            }
            s_part[tid] = a0 + a1;
        }
        __syncthreads();

        if (tid < 128) {
            float zv = s_part[tid] + s_part[128 + tid] + bias2;
            kout[5 + tid] = scl * (0.1f * tanhf(1e-4f * zv));
        }
        if (tid == 0) {
            float S = yv[0], E = yv[1], I = yv[2], A = yv[3];
            float LL = 0.5f * I + A;                       // ee=0, (1-q)=0.5, dd=1
            float bSL = s_beta * S * LL;
            kout[0] = -bSL;
            kout[1] = bSL - 0.526f * E;
            kout[2] = fmaf((float)(0.667 * 0.526), E, -(0.244f * I));
            kout[3] = fmaf((float)((1.0 - 0.667) * 0.526), E, -(0.244f * A));
            kout[4] = fmaf((float)(0.98 * 0.244), I, 0.244f * A);
        }
        __syncthreads();
    };

    const float C2 = 0.161f, C3 = 0.327f, C4 = 0.9f;
    const float C5 = (float)0.9800255409045097;
    const float A21 = 0.161f;
    const float A31 = (float)-0.008480655492356989, A32 = (float)0.335480655492357;
    const float A41 = (float)2.8971530571054935,  A42 = (float)-6.359448489975075,
                A43 = (float)4.3622954328695815;
    const float A51 = (float)5.325864828439257,   A52 = (float)-11.748883564062828,
                A53 = (float)7.4955393428898365,  A54 = (float)-0.09249506636175525;
    const float A61 = (float)5.86145544294642,    A62 = (float)-12.92096931784711,
                A63 = (float)8.159367898576159,   A64 = (float)-0.071584973281401,
                A65 = (float)-0.028269050394068383;
    const float B1 = (float)0.09646076681806523, B2 = 0.01f,
                B3 = (float)0.4798896504144996,  B4 = (float)1.379008574103742,
                B5 = (float)-3.290069515436081,  B6 = (float)2.324710524099774;

    auto tsit5 = [&](float tt, float h) {
        vf(tt, s_y, s_k[0]);
        if (tid < 133) s_tmp[tid] = s_y[tid] + h * (A21 * s_k[0][tid]);
        __syncthreads();
        vf(tt + C2 * h, s_tmp, s_k[1]);
        if (tid < 133) s_tmp[tid] = s_y[tid] + h * (A31 * s_k[0][tid] + A32 * s_k[1][tid]);
        __syncthreads();
        vf(tt + C3 * h, s_tmp, s_k[2]);
        if (tid < 133) s_tmp[tid] = s_y[tid] + h * (A41 * s_k[0][tid] + A42 * s_k[1][tid]
                                                  + A43 * s_k[2][tid]);
        __syncthreads();
        vf(tt + C4 * h, s_tmp, s_k[3]);
        if (tid < 133) s_tmp[tid] = s_y[tid] + h * (A51 * s_k[0][tid] + A52 * s_k[1][tid]
                                                  + A53 * s_k[2][tid] + A54 * s_k[3][tid]);
        __syncthreads();
        vf(tt + C5 * h, s_tmp, s_k[4]);
        if (tid < 133) s_tmp[tid] = s_y[tid] + h * (A61 * s_k[0][tid] + A62 * s_k[1][tid]
                                                  + A63 * s_k[2][tid] + A64 * s_k[3][tid]
                                                  + A65 * s_k[4][tid]);
        __syncthreads();
        vf(tt + h, s_tmp, s_k[5]);
        if (tid < 133) s_y[tid] = s_y[tid] + h * (B1 * s_k[0][tid] + B2 * s_k[1][tid]
                                                + B3 * s_k[2][tid] + B4 * s_k[3][tid]
                                                + B5 * s_k[4][tid] + B6 * s_k[5][tid]);
        __syncthreads();
    };

    float t0v = 0.f;
    for (int s = 0; s < 64; ++s) {
        float tn = ts[b * 64 + s];
        float dt = (tn - t0v) * 0.5f;   // K_SUB = 2
        #pragma unroll
        for (int sub = 0; sub < 2; ++sub) {
            tsit5(t0v + (float)sub * dt, dt);
        }
        t0v = tn;
        if (tid < 5)   out[(b * 64 + s) * 5 + tid] = s_y[tid];
        if (tid < 128) out[OFF_H + (b * 64 + s) * 128 + tid] = s_y[5 + tid];
    }
}

extern "C" void kernel_launch(void* const* d_in, const int* in_sizes, int n_in,
                              void* d_out, int out_size) {
    const float* ts      = (const float*)d_in[0];
    const float* ys      = (const float*)d_in[1];
    const float* scale   = (const float*)d_in[2];
    const float* mlp_w0  = (const float*)d_in[3];
    const float* mlp_b0  = (const float*)d_in[4];
    const float* mlp_w1  = (const float*)d_in[5];
    const float* mlp_b1  = (const float*)d_in[6];
    const float* mlp_w2  = (const float*)d_in[7];
    const float* mlp_b2  = (const float*)d_in[8];
    const float* gru_wih = (const float*)d_in[9];
    const float* gru_whh = (const float*)d_in[10];
    const float* gru_b   = (const float*)d_in[11];
    const float* gru_bn  = (const float*)d_in[12];
    const float* htl_w   = (const float*)d_in[13];
    const float* htl_b   = (const float*)d_in[14];
    const float* htb_w   = (const float*)d_in[15];
    const float* htb_b   = (const float*)d_in[16];
    const float* lti_w   = (const float*)d_in[17];
    const float* lti_b   = (const float*)d_in[18];
    const float* lth_w   = (const float*)d_in[19];
    const float* lth_b   = (const float*)d_in[20];

    prep_kernel<<<96, 256>>>(mlp_w0, mlp_w1, mlp_w2, gru_wih, gru_whh);
    solve_kernel<<<64, 256>>>(ts, ys, scale, mlp_b0, mlp_b1, mlp_b2,
                              gru_b, gru_bn, htl_w, htl_b, htb_w, htb_b,
                              lti_w, lti_b, lth_w, lth_b, (float*)d_out);
}

// round 4
// speedup vs baseline: 1.0449x; 1.0449x over previous
#include <cuda_runtime.h>
#include <cuda_bf16.h>

// Dims: B=64, T=64, D=32, H=128, W=256, L=64, K_SUB=2

// ---------------- device scratch ----------------
// GRU weights: fp32 float4-packed along K (row-major in out-dim, K-major layout)
__device__ float4 g_wihq[ 9 * 384];   // (384,33) pad K->36
__device__ float4 g_whhq[32 * 384];   // (384,128)
// MLP weights: bf16 packed, uint4 = 8 bf16 along K, layout [k8][row]
__device__ uint4  g_w0b[18 * 256];    // (256,129) pad K->144
__device__ uint4  g_w1b[32 * 256];    // (256,256)
__device__ uint4  g_w2b[32 * 128];    // (128,256)

__device__ __forceinline__ unsigned pk_bf2(float a, float b) {
    unsigned lo = (unsigned)__bfloat16_as_ushort(__float2bfloat16_rn(a));
    unsigned hi = (unsigned)__bfloat16_as_ushort(__float2bfloat16_rn(b));
    return (hi << 16) | lo;
}
__device__ __forceinline__ float bf_lo(unsigned u) { return __uint_as_float(u << 16); }
__device__ __forceinline__ float bf_hi(unsigned u) { return __uint_as_float(u & 0xffff0000u); }

__global__ void prep_kernel(const float* __restrict__ w0, const float* __restrict__ w1,
                            const float* __restrict__ w2, const float* __restrict__ wih,
                            const float* __restrict__ whh)
{
    int i0 = blockIdx.x * blockDim.x + threadIdx.x;
    int stride = gridDim.x * blockDim.x;

    // w0 bf16: K=129 padded to 144
    for (int idx = i0; idx < 18 * 256; idx += stride) {
        int k8 = idx >> 8, r = idx & 255, kb = 8 * k8;
        float f[8];
        #pragma unroll
        for (int j = 0; j < 8; ++j) f[j] = (kb + j < 129) ? w0[r * 129 + kb + j] : 0.f;
        uint4 v;
        v.x = pk_bf2(f[0], f[1]); v.y = pk_bf2(f[2], f[3]);
        v.z = pk_bf2(f[4], f[5]); v.w = pk_bf2(f[6], f[7]);
        g_w0b[idx] = v;
    }
    // w1 bf16: K=256
    for (int idx = i0; idx < 32 * 256; idx += stride) {
        int k8 = idx >> 8, r = idx & 255, kb = 8 * k8;
        uint4 v;
        v.x = pk_bf2(w1[r * 256 + kb + 0], w1[r * 256 + kb + 1]);
        v.y = pk_bf2(w1[r * 256 + kb + 2], w1[r * 256 + kb + 3]);
        v.z = pk_bf2(w1[r * 256 + kb + 4], w1[r * 256 + kb + 5]);
        v.w = pk_bf2(w1[r * 256 + kb + 6], w1[r * 256 + kb + 7]);
        g_w1b[idx] = v;
    }
    // w2 bf16: K=256
    for (int idx = i0; idx < 32 * 128; idx += stride) {
        int k8 = idx >> 7, r = idx & 127, kb = 8 * k8;
        uint4 v;
        v.x = pk_bf2(w2[r * 256 + kb + 0], w2[r * 256 + kb + 1]);
        v.y = pk_bf2(w2[r * 256 + kb + 2], w2[r * 256 + kb + 3]);
        v.z = pk_bf2(w2[r * 256 + kb + 4], w2[r * 256 + kb + 5]);
        v.w = pk_bf2(w2[r * 256 + kb + 6], w2[r * 256 + kb + 7]);
        g_w2b[idx] = v;
    }
    // GRU fp32 packs
    for (int idx = i0; idx < 9 * 384; idx += stride) {
        int k4 = idx / 384, j = idx % 384, k = 4 * k4;
        float4 v;
        v.x = (k + 0 < 33) ? wih[j * 33 + k + 0] : 0.f;
        v.y = (k + 1 < 33) ? wih[j * 33 + k + 1] : 0.f;
        v.z = (k + 2 < 33) ? wih[j * 33 + k + 2] : 0.f;
        v.w = (k + 3 < 33) ? wih[j * 33 + k + 3] : 0.f;
        g_wihq[idx] = v;
    }
    for (int idx = i0; idx < 32 * 384; idx += stride) {
        int k4 = idx / 384, j = idx % 384, k = 4 * k4;
        g_whhq[idx] = make_float4(whh[j * 128 + k], whh[j * 128 + k + 1],
                                  whh[j * 128 + k + 2], whh[j * 128 + k + 3]);
    }
}

__device__ __forceinline__ float softplusf(float x) {
    return fmaxf(x, 0.f) + log1pf(expf(-fabsf(x)));
}
__device__ __forceinline__ float sigmoidf(float x) {
    return 1.f / (1.f + expf(-x));
}

// dynamic smem: s_w0 (18*256 uint4 = 73728B) || s_w1 (32*256 uint4 = 131072B)
#define DYN_SMEM_BYTES (18 * 256 * 16 + 32 * 256 * 16)

__global__ void __launch_bounds__(512, 1)
solve_kernel(const float* __restrict__ ts, const float* __restrict__ ys,
             const float* __restrict__ scale,
             const float* __restrict__ mlp_b0, const float* __restrict__ mlp_b1,
             const float* __restrict__ mlp_b2,
             const float* __restrict__ gru_b, const float* __restrict__ gru_bn,
             const float* __restrict__ htl_w, const float* __restrict__ htl_b,
             const float* __restrict__ htb_w, const float* __restrict__ htb_b,
             const float* __restrict__ lti_w, const float* __restrict__ lti_b,
             const float* __restrict__ lth_w, const float* __restrict__ lth_b,
             float* __restrict__ out)
{
    const int b = blockIdx.x;
    const int tid = threadIdx.x;

    extern __shared__ uint4 s_dyn[];
    uint4* s_w0 = s_dyn;                 // [18][256]
    uint4* s_w1 = s_dyn + 18 * 256;      // [32][256]

    __shared__ __align__(16) float s_xg[36];
    __shared__ __align__(16) float s_hid[128];
    __shared__ float s_ih[384], s_hh[384];
    __shared__ __align__(16) float s_y[136];
    __shared__ __align__(16) float s_tmp[136];
    __shared__ __align__(16) float s_k[6][136];
    __shared__ __align__(16) float s_xv[144];
    __shared__ __align__(16) float s_a0[256];
    __shared__ __align__(16) float s_a1[256];
    __shared__ float s_part[512];
    __shared__ float s_z0[64];
    __shared__ float s_beta;

    const int OFF_H = 64 * 64 * 5;
    const int OFF_Z = OFF_H + 64 * 64 * 128;

    // copy MLP weights into smem
    for (int i = tid; i < 18 * 256; i += 512) s_w0[i] = g_w0b[i];
    for (int i = tid; i < 32 * 256; i += 512) s_w1[i] = g_w1b[i];

    // w2 in registers: 4 threads per row, each 64 K = 8 uint4
    uint4 w2r[8];
    {
        int r = tid & 127, q = tid >> 7;
        #pragma unroll
        for (int j = 0; j < 8; ++j) w2r[j] = g_w2b[(q * 8 + j) * 128 + r];
    }

    if (tid < 128) s_hid[tid] = 0.f;
    if (tid >= 33 && tid < 36) s_xg[tid] = 0.f;
    if (tid >= 129 && tid < 144) s_xv[tid] = 0.f;
    __syncthreads();

    // ---------------- GRU over reversed sequence ----------------
    for (int step = 0; step < 64; ++step) {
        int r = 63 - step;
        if (tid == 0) s_xg[0] = ts[b * 64 + r];
        if (tid >= 1 && tid < 33) s_xg[tid] = ys[(b * 64 + r) * 32 + (tid - 1)];
        __syncthreads();

        if (tid < 384) {
            const float4* xg4 = (const float4*)s_xg;
            const float4* h4  = (const float4*)s_hid;
            int row = tid;
            float a0 = gru_b[row], a1 = 0.f;
            #pragma unroll
            for (int k = 0; k < 9; ++k) {
                float4 w = g_wihq[k * 384 + row];
                float4 x = xg4[k];
                a0 = fmaf(w.x, x.x, fmaf(w.z, x.z, a0));
                a1 = fmaf(w.y, x.y, fmaf(w.w, x.w, a1));
            }
            float b0 = 0.f, b1 = 0.f;
            #pragma unroll 8
            for (int k = 0; k < 32; ++k) {
                float4 w = g_whhq[k * 384 + row];
                float4 x = h4[k];
                b0 = fmaf(w.x, x.x, fmaf(w.z, x.z, b0));
                b1 = fmaf(w.y, x.y, fmaf(w.w, x.w, b1));
            }
            s_ih[row] = a0 + a1;
            s_hh[row] = b0 + b1;
        }
        __syncthreads();
        if (tid < 128) {
            float rr = sigmoidf(s_ih[tid] + s_hh[tid]);
            float zz = sigmoidf(s_ih[128 + tid] + s_hh[128 + tid]);
            float nn = tanhf(s_ih[256 + tid] + rr * (s_hh[256 + tid] + gru_bn[tid]));
            s_hid[tid] = nn + zz * (s_hid[tid] - nn);
        }
        __syncthreads();
    }

    // ---------------- head: z0, h0, y0 ----------------
    if (tid < 64) {
        float acc = htl_b[tid];
        #pragma unroll 8
        for (int k = 0; k < 128; ++k) acc = fmaf(htl_w[tid * 128 + k], s_hid[k], acc);
        s_z0[tid] = acc;
        out[OFF_Z + b * 64 + tid] = acc;
    }
    __syncthreads();
    if (tid < 128) {
        float acc = lth_b[tid];
        #pragma unroll 8
        for (int k = 0; k < 64; ++k) acc = fmaf(lth_w[tid * 64 + k], s_z0[k], acc);
        s_y[5 + tid] = acc;
    }
    if (tid == 0) {
        float lg[5], mx = -1e30f;
        #pragma unroll
        for (int m = 0; m < 5; ++m) {
            float acc = lti_b[m];
            for (int k = 0; k < 64; ++k) acc = fmaf(lti_w[m * 64 + k], s_z0[k], acc);
            lg[m] = acc;
            mx = fmaxf(mx, acc);
        }
        float sum = 0.f;
        #pragma unroll
        for (int m = 0; m < 5; ++m) { float e = expf(lg[m] - mx); s_y[m] = e; sum += e; }
        #pragma unroll
        for (int m = 0; m < 5; ++m) s_y[m] /= sum;
    }
    __syncthreads();

    // ---------------- ODE solve ----------------
    const float scl   = scale[0];
    const float bias0 = (tid < 256) ? mlp_b0[tid] : 0.f;
    const float bias1 = (tid < 256) ? mlp_b1[tid] : 0.f;
    const float bias2 = (tid < 128) ? mlp_b2[tid] : 0.f;
    const float htbb  = htb_b[0];

    auto vf = [&](float tt, const float* yv, float* kout) {
        if (tid == 0) s_xv[0] = tt;
        if (tid < 128) s_xv[1 + tid] = yv[5 + tid];
        if (tid < 32) {
            float p = fmaf(htb_w[tid], yv[5 + tid],
                      fmaf(htb_w[tid + 32], yv[37 + tid],
                      fmaf(htb_w[tid + 64], yv[69 + tid],
                           htb_w[tid + 96] * yv[101 + tid])));
            #pragma unroll
            for (int o = 16; o > 0; o >>= 1) p += __shfl_xor_sync(0xffffffffu, p, o);
            if (tid == 0) s_beta = sigmoidf(0.01f * (p + htbb));
        }
        __syncthreads();

        // layer 0: W0(256x129 pad144) @ xv, K split across halves
        {
            int r = tid & 255, half = tid >> 8;
            const float4* xv4 = (const float4*)s_xv;
            float a0 = 0.f, a1 = 0.f, a2 = 0.f, a3 = 0.f;
            #pragma unroll
            for (int j = 0; j < 9; ++j) {
                int k8 = half * 9 + j;
                uint4 w = s_w0[k8 * 256 + r];
                float4 xa = xv4[2 * k8], xb = xv4[2 * k8 + 1];
                a0 = fmaf(bf_lo(w.x), xa.x, a0);
                a1 = fmaf(bf_hi(w.x), xa.y, a1);
                a2 = fmaf(bf_lo(w.y), xa.z, a2);
                a3 = fmaf(bf_hi(w.y), xa.w, a3);
                a0 = fmaf(bf_lo(w.z), xb.x, a0);
                a1 = fmaf(bf_hi(w.z), xb.y, a1);
                a2 = fmaf(bf_lo(w.w), xb.z, a2);
                a3 = fmaf(bf_hi(w.w), xb.w, a3);
            }
            s_part[tid] = (a0 + a1) + (a2 + a3);
        }
        __syncthreads();
        if (tid < 256) s_a0[tid] = softplusf(s_part[tid] + s_part[tid + 256] + bias0);
        __syncthreads();

        // layer 1: W1(256x256) @ a0, K split across halves
        {
            int r = tid & 255, half = tid >> 8;
            const float4* a4 = (const float4*)s_a0;
            float a0 = 0.f, a1 = 0.f, a2 = 0.f, a3 = 0.f;
            #pragma unroll
            for (int j = 0; j < 16; ++j) {
                int k8 = half * 16 + j;
                uint4 w = s_w1[k8 * 256 + r];
                float4 xa = a4[2 * k8], xb = a4[2 * k8 + 1];
                a0 = fmaf(bf_lo(w.x), xa.x, a0);
                a1 = fmaf(bf_hi(w.x), xa.y, a1);
                a2 = fmaf(bf_lo(w.y), xa.z, a2);
                a3 = fmaf(bf_hi(w.y), xa.w, a3);
                a0 = fmaf(bf_lo(w.z), xb.x, a0);
                a1 = fmaf(bf_hi(w.z), xb.y, a1);
                a2 = fmaf(bf_lo(w.w), xb.z, a2);
                a3 = fmaf(bf_hi(w.w), xb.w, a3);
            }
            s_part[tid] = (a0 + a1) + (a2 + a3);
        }
        __syncthreads();
        if (tid < 256) s_a1[tid] = softplusf(s_part[tid] + s_part[tid + 256] + bias1);
        __syncthreads();

        // layer 2: W2(128x256) @ a1, 4 threads per row (weights in registers)
        {
            int q = tid >> 7;
            const float4* a4 = (const float4*)s_a1;
            float a0 = 0.f, a1 = 0.f, a2 = 0.f, a3 = 0.f;
            #pragma unroll
            for (int j = 0; j < 8; ++j) {
                int k8 = q * 8 + j;
                uint4 w = w2r[j];
                float4 xa = a4[2 * k8], xb = a4[2 * k8 + 1];
                a0 = fmaf(bf_lo(w.x), xa.x, a0);
                a1 = fmaf(bf_hi(w.x), xa.y, a1);
                a2 = fmaf(bf_lo(w.y), xa.z, a2);
                a3 = fmaf(bf_hi(w.y), xa.w, a3);
                a0 = fmaf(bf_lo(w.z), xb.x, a0);
                a1 = fmaf(bf_hi(w.z), xb.y, a1);
                a2 = fmaf(bf_lo(w.w), xb.z, a2);
                a3 = fmaf(bf_hi(w.w), xb.w, a3);
            }
            s_part[tid] = (a0 + a1) + (a2 + a3);
        }
        __syncthreads();

        if (tid < 128) {
            float zv = s_part[tid] + s_part[tid + 128] + s_part[tid + 256]
                     + s_part[tid + 384] + bias2;
            kout[5 + tid] = scl * (0.1f * tanhf(1e-4f * zv));
        }
        if (tid == 0) {
            float S = yv[0], E = yv[1], I = yv[2], A = yv[3];
            float LL = 0.5f * I + A;
            float bSL = s_beta * S * LL;
            kout[0] = -bSL;
            kout[1] = bSL - 0.526f * E;
            kout[2] = fmaf((float)(0.667 * 0.526), E, -(0.244f * I));
            kout[3] = fmaf((float)((1.0 - 0.667) * 0.526), E, -(0.244f * A));
            kout[4] = fmaf((float)(0.98 * 0.244), I, 0.244f * A);
        }
        __syncthreads();
    };

    const float C2 = 0.161f, C3 = 0.327f, C4 = 0.9f;
    const float C5 = (float)0.9800255409045097;
    const float A21 = 0.161f;
    const float A31 = (float)-0.008480655492356989, A32 = (float)0.335480655492357;
    const float A41 = (float)2.8971530571054935,  A42 = (float)-6.359448489975075,
                A43 = (float)4.3622954328695815;
    const float A51 = (float)5.325864828439257,   A52 = (float)-11.748883564062828,
                A53 = (float)7.4955393428898365,  A54 = (float)-0.09249506636175525;
    const float A61 = (float)5.86145544294642,    A62 = (float)-12.92096931784711,
                A63 = (float)8.159367898576159,   A64 = (float)-0.071584973281401,
                A65 = (float)-0.028269050394068383;
    const float B1 = (float)0.09646076681806523, B2 = 0.01f,
                B3 = (float)0.4798896504144996,  B4 = (float)1.379008574103742,
                B5 = (float)-3.290069515436081,  B6 = (float)2.324710524099774;

    auto tsit5 = [&](float tt, float h) {
        vf(tt, s_y, s_k[0]);
        if (tid < 133) s_tmp[tid] = s_y[tid] + h * (A21 * s_k[0][tid]);
        __syncthreads();
        vf(tt + C2 * h, s_tmp, s_k[1]);
        if (tid < 133) s_tmp[tid] = s_y[tid] + h * (A31 * s_k[0][tid] + A32 * s_k[1][tid]);
        __syncthreads();
        vf(tt + C3 * h, s_tmp, s_k[2]);
        if (tid < 133) s_tmp[tid] = s_y[tid] + h * (A41 * s_k[0][tid] + A42 * s_k[1][tid]
                                                  + A43 * s_k[2][tid]);
        __syncthreads();
        vf(tt + C4 * h, s_tmp, s_k[3]);
        if (tid < 133) s_tmp[tid] = s_y[tid] + h * (A51 * s_k[0][tid] + A52 * s_k[1][tid]
                                                  + A53 * s_k[2][tid] + A54 * s_k[3][tid]);
        __syncthreads();
        vf(tt + C5 * h, s_tmp, s_k[4]);
        if (tid < 133) s_tmp[tid] = s_y[tid] + h * (A61 * s_k[0][tid] + A62 * s_k[1][tid]
                                                  + A63 * s_k[2][tid] + A64 * s_k[3][tid]
                                                  + A65 * s_k[4][tid]);
        __syncthreads();
        vf(tt + h, s_tmp, s_k[5]);
        if (tid < 133) s_y[tid] = s_y[tid] + h * (B1 * s_k[0][tid] + B2 * s_k[1][tid]
                                                + B3 * s_k[2][tid] + B4 * s_k[3][tid]
                                                + B5 * s_k[4][tid] + B6 * s_k[5][tid]);
        __syncthreads();
    };

    float t0v = 0.f;
    for (int s = 0; s < 64; ++s) {
        float tn = ts[b * 64 + s];
        float dt = (tn - t0v) * 0.5f;   // K_SUB = 2
        #pragma unroll
        for (int sub = 0; sub < 2; ++sub) {
            tsit5(t0v + (float)sub * dt, dt);
        }
        t0v = tn;
        if (tid < 5)   out[(b * 64 + s) * 5 + tid] = s_y[tid];
        if (tid < 128) out[OFF_H + (b * 64 + s) * 128 + tid] = s_y[5 + tid];
    }
}

extern "C" void kernel_launch(void* const* d_in, const int* in_sizes, int n_in,
                              void* d_out, int out_size) {
    const float* ts      = (const float*)d_in[0];
    const float* ys      = (const float*)d_in[1];
    const float* scale   = (const float*)d_in[2];
    const float* mlp_w0  = (const float*)d_in[3];
    const float* mlp_b0  = (const float*)d_in[4];
    const float* mlp_w1  = (const float*)d_in[5];
    const float* mlp_b1  = (const float*)d_in[6];
    const float* mlp_w2  = (const float*)d_in[7];
    const float* mlp_b2  = (const float*)d_in[8];
    const float* gru_wih = (const float*)d_in[9];
    const float* gru_whh = (const float*)d_in[10];
    const float* gru_b   = (const float*)d_in[11];
    const float* gru_bn  = (const float*)d_in[12];
    const float* htl_w   = (const float*)d_in[13];
    const float* htl_b   = (const float*)d_in[14];
    const float* htb_w   = (const float*)d_in[15];
    const float* htb_b   = (const float*)d_in[16];
    const float* lti_w   = (const float*)d_in[17];
    const float* lti_b   = (const float*)d_in[18];
    const float* lth_w   = (const float*)d_in[19];
    const float* lth_b   = (const float*)d_in[20];

    static int attr_set = 0;
    if (!attr_set) {
        cudaFuncSetAttribute(solve_kernel,
                             cudaFuncAttributeMaxDynamicSharedMemorySize,
                             DYN_SMEM_BYTES);
        attr_set = 1;
    }

    prep_kernel<<<96, 256>>>(mlp_w0, mlp_w1, mlp_w2, gru_wih, gru_whh);
    solve_kernel<<<64, 512, DYN_SMEM_BYTES>>>(ts, ys, scale, mlp_b0, mlp_b1, mlp_b2,
                              gru_b, gru_bn, htl_w, htl_b, htb_w, htb_b,
                              lti_w, lti_b, lth_w, lth_b, (float*)d_out);
}

// round 5
// speedup vs baseline: 1.0695x; 1.0236x over previous
#include <cuda_runtime.h>
#include <cuda_bf16.h>

// Dims: B=64, T=64, D=32, H=128, W=256, L=64, K_SUB=2

// ---------------- device scratch ----------------
// GRU weights: fp32 float4-packed along K
__device__ float4 g_wihq[ 9 * 384];
__device__ float4 g_whhq[32 * 384];
// MLP weights bf16, laid out for the within-warp K-split consumers:
// w0: rows 256, K pad 144, 2 lanes/row (half=72K=9 uint4). g_w0p[k9*512 + u]
//     u = warp*32+lane, row = 16*(u>>5) + ((u&31)>>1), half = u&1
__device__ uint4 g_w0p[ 9 * 512];
// w1: rows 256, K 256, 2 lanes/row (half=128K=16 uint4). g_w1p[k16*512 + u]
__device__ uint4 g_w1p[16 * 512];
// w2: rows 128, K 256, 4 lanes/row (quarter=64K=8 uint4), per-thread regs:
//     g_w2p[t*8 + j], t: row = 8*(t>>5) + ((t&31)>>2), q = t&3
__device__ uint4 g_w2p[512 * 8];

__device__ __forceinline__ unsigned pk_bf2(float a, float b) {
    unsigned lo = (unsigned)__bfloat16_as_ushort(__float2bfloat16_rn(a));
    unsigned hi = (unsigned)__bfloat16_as_ushort(__float2bfloat16_rn(b));
    return (hi << 16) | lo;
}

__global__ void prep_kernel(const float* __restrict__ w0, const float* __restrict__ w1,
                            const float* __restrict__ w2, const float* __restrict__ wih,
                            const float* __restrict__ whh)
{
    int i0 = blockIdx.x * blockDim.x + threadIdx.x;
    int stride = gridDim.x * blockDim.x;

    // w0p
    for (int idx = i0; idx < 9 * 512; idx += stride) {
        int k9 = idx / 512, u = idx % 512;
        int row = 16 * (u >> 5) + ((u & 31) >> 1);
        int half = u & 1;
        int kb = half * 72 + k9 * 8;
        float f[8];
        #pragma unroll
        for (int j = 0; j < 8; ++j) {
            int k = kb + j;
            f[j] = (k < 129) ? w0[row * 129 + k] : 0.f;
        }
        uint4 v;
        v.x = pk_bf2(f[0], f[1]); v.y = pk_bf2(f[2], f[3]);
        v.z = pk_bf2(f[4], f[5]); v.w = pk_bf2(f[6], f[7]);
        g_w0p[idx] = v;
    }
    // w1p
    for (int idx = i0; idx < 16 * 512; idx += stride) {
        int k16 = idx / 512, u = idx % 512;
        int row = 16 * (u >> 5) + ((u & 31) >> 1);
        int half = u & 1;
        int kb = half * 128 + k16 * 8;
        uint4 v;
        v.x = pk_bf2(w1[row * 256 + kb + 0], w1[row * 256 + kb + 1]);
        v.y = pk_bf2(w1[row * 256 + kb + 2], w1[row * 256 + kb + 3]);
        v.z = pk_bf2(w1[row * 256 + kb + 4], w1[row * 256 + kb + 5]);
        v.w = pk_bf2(w1[row * 256 + kb + 6], w1[row * 256 + kb + 7]);
        g_w1p[idx] = v;
    }
    // w2p
    for (int idx = i0; idx < 512 * 8; idx += stride) {
        int t = idx >> 3, j = idx & 7;
        int row = 8 * (t >> 5) + ((t & 31) >> 2);
        int q = t & 3;
        int kb = q * 64 + j * 8;
        uint4 v;
        v.x = pk_bf2(w2[row * 256 + kb + 0], w2[row * 256 + kb + 1]);
        v.y = pk_bf2(w2[row * 256 + kb + 2], w2[row * 256 + kb + 3]);
        v.z = pk_bf2(w2[row * 256 + kb + 4], w2[row * 256 + kb + 5]);
        v.w = pk_bf2(w2[row * 256 + kb + 6], w2[row * 256 + kb + 7]);
        g_w2p[idx] = v;
    }
    // GRU fp32 packs
    for (int idx = i0; idx < 9 * 384; idx += stride) {
        int k4 = idx / 384, j = idx % 384, k = 4 * k4;
        float4 v;
        v.x = (k + 0 < 33) ? wih[j * 33 + k + 0] : 0.f;
        v.y = (k + 1 < 33) ? wih[j * 33 + k + 1] : 0.f;
        v.z = (k + 2 < 33) ? wih[j * 33 + k + 2] : 0.f;
        v.w = (k + 3 < 33) ? wih[j * 33 + k + 3] : 0.f;
        g_wihq[idx] = v;
    }
    for (int idx = i0; idx < 32 * 384; idx += stride) {
        int k4 = idx / 384, j = idx % 384, k = 4 * k4;
        g_whhq[idx] = make_float4(whh[j * 128 + k], whh[j * 128 + k + 1],
                                  whh[j * 128 + k + 2], whh[j * 128 + k + 3]);
    }
}

// ---------------- math helpers ----------------
typedef unsigned long long ull;

// bf16x2 word -> packed f32x2 (lo = u<<16, hi = u & 0xffff0000)
__device__ __forceinline__ ull bfpair(unsigned w) {
    ull r;
    asm("{\n\t"
        ".reg .b32 lo, hi;\n\t"
        "shl.b32 lo, %1, 16;\n\t"
        "and.b32 hi, %1, 0xffff0000;\n\t"
        "mov.b64 %0, {lo, hi};\n\t"
        "}" : "=l"(r) : "r"(w));
    return r;
}
__device__ __forceinline__ ull ffma2(ull a, ull b, ull c) {
    ull r;
    asm("fma.rn.f32x2 %0, %1, %2, %3;" : "=l"(r) : "l"(a), "l"(b), "l"(c));
    return r;
}
__device__ __forceinline__ float acc_sum(ull a, ull b) {
    float alo, ahi, blo, bhi;
    asm("mov.b64 {%0, %1}, %2;" : "=f"(alo), "=f"(ahi) : "l"(a));
    asm("mov.b64 {%0, %1}, %2;" : "=f"(blo), "=f"(bhi) : "l"(b));
    return (alo + ahi) + (blo + bhi);
}
__device__ __forceinline__ float tanh_fast(float x) {
    float y;
    asm("tanh.approx.f32 %0, %1;" : "=f"(y) : "f"(x));
    return y;
}
__device__ __forceinline__ float softplus_fast(float x) {
    return fmaxf(x, 0.f) + __logf(1.f + __expf(-fabsf(x)));
}
__device__ __forceinline__ float sigmoid_fast(float x) {
    return 1.f / (1.f + __expf(-x));
}
// precise versions for GRU
__device__ __forceinline__ float sigmoidp(float x) { return 1.f / (1.f + expf(-x)); }

// dynamic smem: s_w0 (9*512 uint4) || s_w1 (16*512 uint4)
#define SW0_N (9 * 512)
#define SW1_N (16 * 512)
#define DYN_SMEM_BYTES ((SW0_N + SW1_N) * 16)

__global__ void __launch_bounds__(512, 1)
solve_kernel(const float* __restrict__ ts, const float* __restrict__ ys,
             const float* __restrict__ scale,
             const float* __restrict__ mlp_b0, const float* __restrict__ mlp_b1,
             const float* __restrict__ mlp_b2,
             const float* __restrict__ gru_b, const float* __restrict__ gru_bn,
             const float* __restrict__ htl_w, const float* __restrict__ htl_b,
             const float* __restrict__ htb_w, const float* __restrict__ htb_b,
             const float* __restrict__ lti_w, const float* __restrict__ lti_b,
             const float* __restrict__ lth_w, const float* __restrict__ lth_b,
             float* __restrict__ out)
{
    const int b = blockIdx.x;
    const int tid = threadIdx.x;

    extern __shared__ uint4 s_dyn[];
    uint4* s_w0 = s_dyn;            // [9][512]
    uint4* s_w1 = s_dyn + SW0_N;    // [16][512]

    __shared__ __align__(16) float s_xg[36];
    __shared__ __align__(16) float s_hid[128];
    __shared__ float s_ih[384], s_hh[384];
    __shared__ __align__(16) float s_y[136];
    __shared__ __align__(16) float s_tmp[136];
    __shared__ __align__(16) float s_k[6][136];
    __shared__ __align__(16) float s_xv[144];
    __shared__ __align__(16) float s_a0[256];
    __shared__ __align__(16) float s_a1[256];
    __shared__ float s_z0[64];
    __shared__ float s_beta;

    const int OFF_H = 64 * 64 * 5;
    const int OFF_Z = OFF_H + 64 * 64 * 128;

    // load packed MLP weights into smem / registers
    for (int i = tid; i < SW0_N; i += 512) s_w0[i] = g_w0p[i];
    for (int i = tid; i < SW1_N; i += 512) s_w1[i] = g_w1p[i];

    uint4 w2r[8];
    #pragma unroll
    for (int j = 0; j < 8; ++j) w2r[j] = g_w2p[tid * 8 + j];

    // per-thread role constants
    const int lane  = tid & 31;
    const int half  = lane & 1;              // layers 0/1: K half
    const int rowA  = 16 * (tid >> 5) + (lane >> 1);   // 0..255
    const int q     = lane & 3;              // layer 2: K quarter
    const int rowB  = 8 * (tid >> 5) + (lane >> 2);    // 0..127

    const float b0r = mlp_b0[rowA];
    const float b1r = mlp_b1[rowA];
    const float b2r = mlp_b2[rowB];

    // beta dot weights (warp 0 only)
    float hw0 = 0.f, hw1 = 0.f, hw2 = 0.f, hw3 = 0.f, htbb = 0.f;
    if (tid < 32) {
        hw0 = htb_w[tid]; hw1 = htb_w[tid + 32];
        hw2 = htb_w[tid + 64]; hw3 = htb_w[tid + 96];
        htbb = htb_b[0];
    }

    if (tid < 128) s_hid[tid] = 0.f;
    if (tid >= 33 && tid < 36) s_xg[tid] = 0.f;
    if (tid >= 129 && tid < 144) s_xv[tid] = 0.f;
    __syncthreads();

    // ---------------- GRU over reversed sequence ----------------
    for (int step = 0; step < 64; ++step) {
        int r = 63 - step;
        if (tid == 0) s_xg[0] = ts[b * 64 + r];
        if (tid >= 1 && tid < 33) s_xg[tid] = ys[(b * 64 + r) * 32 + (tid - 1)];
        __syncthreads();

        if (tid < 384) {
            const float4* xg4 = (const float4*)s_xg;
            const float4* h4  = (const float4*)s_hid;
            int row = tid;
            float a0 = gru_b[row], a1 = 0.f;
            #pragma unroll
            for (int k = 0; k < 9; ++k) {
                float4 w = g_wihq[k * 384 + row];
                float4 x = xg4[k];
                a0 = fmaf(w.x, x.x, fmaf(w.z, x.z, a0));
                a1 = fmaf(w.y, x.y, fmaf(w.w, x.w, a1));
            }
            float c0 = 0.f, c1 = 0.f;
            #pragma unroll 8
            for (int k = 0; k < 32; ++k) {
                float4 w = g_whhq[k * 384 + row];
                float4 x = h4[k];
                c0 = fmaf(w.x, x.x, fmaf(w.z, x.z, c0));
                c1 = fmaf(w.y, x.y, fmaf(w.w, x.w, c1));
            }
            s_ih[row] = a0 + a1;
            s_hh[row] = c0 + c1;
        }
        __syncthreads();
        if (tid < 128) {
            float rr = sigmoidp(s_ih[tid] + s_hh[tid]);
            float zz = sigmoidp(s_ih[128 + tid] + s_hh[128 + tid]);
            float nn = tanhf(s_ih[256 + tid] + rr * (s_hh[256 + tid] + gru_bn[tid]));
            s_hid[tid] = nn + zz * (s_hid[tid] - nn);
        }
        __syncthreads();
    }

    // ---------------- head: z0, h0, y0 ----------------
    if (tid < 64) {
        float acc = htl_b[tid];
        #pragma unroll 8
        for (int k = 0; k < 128; ++k) acc = fmaf(htl_w[tid * 128 + k], s_hid[k], acc);
        s_z0[tid] = acc;
        out[OFF_Z + b * 64 + tid] = acc;
    }
    __syncthreads();
    if (tid < 128) {
        float acc = lth_b[tid];
        #pragma unroll 8
        for (int k = 0; k < 64; ++k) acc = fmaf(lth_w[tid * 64 + k], s_z0[k], acc);
        s_y[5 + tid] = acc;
    }
    if (tid == 0) {
        float lg[5], mx = -1e30f;
        #pragma unroll
        for (int m = 0; m < 5; ++m) {
            float acc = lti_b[m];
            for (int k = 0; k < 64; ++k) acc = fmaf(lti_w[m * 64 + k], s_z0[k], acc);
            lg[m] = acc; mx = fmaxf(mx, acc);
        }
        float sum = 0.f;
        #pragma unroll
        for (int m = 0; m < 5; ++m) { float e = expf(lg[m] - mx); s_y[m] = e; sum += e; }
        #pragma unroll
        for (int m = 0; m < 5; ++m) s_y[m] /= sum;
    }
    __syncthreads();

    const float scl = scale[0];

    // fill s_xv from initial state (first vf reads it); s_xv[0] = t0 = 0
    if (tid < 128) s_xv[1 + tid] = s_y[5 + tid];
    if (tid == 256) s_xv[0] = 0.f;
    __syncthreads();

    // ---------------- vf: assumes s_xv ready on entry; 3 internal syncs ----------------
    auto vf = [&](const float* yv, float* kout) {
        // layer 0: 2 lanes/row, K halves of 72 (9 uint4)
        {
            const ulonglong2* xp = (const ulonglong2*)s_xv;
            int xb = half * 18;
            ull a0 = 0ULL, a1 = 0ULL;
            #pragma unroll
            for (int k = 0; k < 9; ++k) {
                uint4 w = s_w0[k * 512 + tid];
                ulonglong2 x0 = xp[xb + 2 * k];
                ulonglong2 x1 = xp[xb + 2 * k + 1];
                a0 = ffma2(bfpair(w.x), x0.x, a0);
                a1 = ffma2(bfpair(w.y), x0.y, a1);
                a0 = ffma2(bfpair(w.z), x1.x, a0);
                a1 = ffma2(bfpair(w.w), x1.y, a1);
            }
            float s = acc_sum(a0, a1);
            s += __shfl_xor_sync(0xffffffffu, s, 1);
            if (!half) s_a0[rowA] = softplus_fast(s + b0r);
        }
        // beta (warp 0, overlapped with layer 0 phase)
        if (tid < 32) {
            float p = fmaf(hw0, s_xv[1 + tid],
                      fmaf(hw1, s_xv[33 + tid],
                      fmaf(hw2, s_xv[65 + tid],
                           hw3 * s_xv[97 + tid])));
            #pragma unroll
            for (int o = 16; o > 0; o >>= 1) p += __shfl_xor_sync(0xffffffffu, p, o);
            if (tid == 0) s_beta = sigmoid_fast(0.01f * (p + htbb));
        }
        __syncthreads();

        // layer 1: 2 lanes/row, K halves of 128 (16 uint4)
        {
            const ulonglong2* xp = (const ulonglong2*)s_a0;
            int xb = half * 32;
            ull a0 = 0ULL, a1 = 0ULL;
            #pragma unroll
            for (int k = 0; k < 16; ++k) {
                uint4 w = s_w1[k * 512 + tid];
                ulonglong2 x0 = xp[xb + 2 * k];
                ulonglong2 x1 = xp[xb + 2 * k + 1];
                a0 = ffma2(bfpair(w.x), x0.x, a0);
                a1 = ffma2(bfpair(w.y), x0.y, a1);
                a0 = ffma2(bfpair(w.z), x1.x, a0);
                a1 = ffma2(bfpair(w.w), x1.y, a1);
            }
            float s = acc_sum(a0, a1);
            s += __shfl_xor_sync(0xffffffffu, s, 1);
            if (!half) s_a1[rowA] = softplus_fast(s + b1r);
        }
        __syncthreads();

        // layer 2: 4 lanes/row, K quarters of 64 (8 uint4 in regs)
        {
            const ulonglong2* xp = (const ulonglong2*)s_a1;
            int xb = q * 16;
            ull a0 = 0ULL, a1 = 0ULL;
            #pragma unroll
            for (int k = 0; k < 8; ++k) {
                uint4 w = w2r[k];
                ulonglong2 x0 = xp[xb + 2 * k];
                ulonglong2 x1 = xp[xb + 2 * k + 1];
                a0 = ffma2(bfpair(w.x), x0.x, a0);
                a1 = ffma2(bfpair(w.y), x0.y, a1);
                a0 = ffma2(bfpair(w.z), x1.x, a0);
                a1 = ffma2(bfpair(w.w), x1.y, a1);
            }
            float s = acc_sum(a0, a1);
            s += __shfl_xor_sync(0xffffffffu, s, 1);
            s += __shfl_xor_sync(0xffffffffu, s, 2);
            if (q == 0)
                kout[5 + rowB] = scl * (0.1f * tanh_fast(1e-4f * (s + b2r)));
        }
        if (tid == 0) {
            float S = yv[0], E = yv[1], I = yv[2], A = yv[3];
            float LL = 0.5f * I + A;
            float bSL = s_beta * S * LL;
            kout[0] = -bSL;
            kout[1] = bSL - 0.526f * E;
            kout[2] = fmaf((float)(0.667 * 0.526), E, -(0.244f * I));
            kout[3] = fmaf((float)((1.0 - 0.667) * 0.526), E, -(0.244f * A));
            kout[4] = fmaf((float)(0.98 * 0.244), I, 0.244f * A);
        }
        __syncthreads();   // kout ready
    };

    const float C2 = 0.161f, C3 = 0.327f, C4 = 0.9f;
    const float C5 = (float)0.9800255409045097;
    const float A21 = 0.161f;
    const float A31 = (float)-0.008480655492356989, A32 = (float)0.335480655492357;
    const float A41 = (float)2.8971530571054935,  A42 = (float)-6.359448489975075,
                A43 = (float)4.3622954328695815;
    const float A51 = (float)5.325864828439257,   A52 = (float)-11.748883564062828,
                A53 = (float)7.4955393428898365,  A54 = (float)-0.09249506636175525;
    const float A61 = (float)5.86145544294642,    A62 = (float)-12.92096931784711,
                A63 = (float)8.159367898576159,   A64 = (float)-0.071584973281401,
                A65 = (float)-0.028269050394068383;
    const float B1 = (float)0.09646076681806523, B2 = 0.01f,
                B3 = (float)0.4798896504144996,  B4 = (float)1.379008574103742,
                B5 = (float)-3.290069515436081,  B6 = (float)2.324710524099774;

    // tsit5: s_xv must hold current y with s_xv[0]=tt on entry.
    // t_after = time of the FIRST vf of the NEXT tsit5 call.
    auto tsit5 = [&](float tt, float h, float t_after) {
        vf(s_y, s_k[0]);
        if (tid < 133) {
            float v = s_y[tid] + h * (A21 * s_k[0][tid]);
            s_tmp[tid] = v;
            if (tid >= 5) s_xv[tid - 4] = v;
        }
        if (tid == 256) s_xv[0] = tt + C2 * h;
        __syncthreads();
        vf(s_tmp, s_k[1]);
        if (tid < 133) {
            float v = s_y[tid] + h * (A31 * s_k[0][tid] + A32 * s_k[1][tid]);
            s_tmp[tid] = v;
            if (tid >= 5) s_xv[tid - 4] = v;
        }
        if (tid == 256) s_xv[0] = tt + C3 * h;
        __syncthreads();
        vf(s_tmp, s_k[2]);
        if (tid < 133) {
            float v = s_y[tid] + h * (A41 * s_k[0][tid] + A42 * s_k[1][tid]
                                    + A43 * s_k[2][tid]);
            s_tmp[tid] = v;
            if (tid >= 5) s_xv[tid - 4] = v;
        }
        if (tid == 256) s_xv[0] = tt + C4 * h;
        __syncthreads();
        vf(s_tmp, s_k[3]);
        if (tid < 133) {
            float v = s_y[tid] + h * (A51 * s_k[0][tid] + A52 * s_k[1][tid]
                                    + A53 * s_k[2][tid] + A54 * s_k[3][tid]);
            s_tmp[tid] = v;
            if (tid >= 5) s_xv[tid - 4] = v;
        }
        if (tid == 256) s_xv[0] = tt + C5 * h;
        __syncthreads();
        vf(s_tmp, s_k[4]);
        if (tid < 133) {
            float v = s_y[tid] + h * (A61 * s_k[0][tid] + A62 * s_k[1][tid]
                                    + A63 * s_k[2][tid] + A64 * s_k[3][tid]
                                    + A65 * s_k[4][tid]);
            s_tmp[tid] = v;
            if (tid >= 5) s_xv[tid - 4] = v;
        }
        if (tid == 256) s_xv[0] = tt + h;
        __syncthreads();
        vf(s_tmp, s_k[5]);
        if (tid < 133) {
            float v = s_y[tid] + h * (B1 * s_k[0][tid] + B2 * s_k[1][tid]
                                    + B3 * s_k[2][tid] + B4 * s_k[3][tid]
                                    + B5 * s_k[4][tid] + B6 * s_k[5][tid]);
            s_y[tid] = v;
            if (tid >= 5) s_xv[tid - 4] = v;
        }
        if (tid == 256) s_xv[0] = t_after;
        __syncthreads();
    };

    float t0v = 0.f;
    for (int s = 0; s < 64; ++s) {
        float tn = ts[b * 64 + s];
        float dt = (tn - t0v) * 0.5f;    // K_SUB = 2
        tsit5(t0v,      dt, t0v + dt);
        tsit5(t0v + dt, dt, tn);
        t0v = tn;
        if (tid < 5)   out[(b * 64 + s) * 5 + tid] = s_y[tid];
        if (tid < 128) out[OFF_H + (b * 64 + s) * 128 + tid] = s_y[5 + tid];
    }
}

extern "C" void kernel_launch(void* const* d_in, const int* in_sizes, int n_in,
                              void* d_out, int out_size) {
    const float* ts      = (const float*)d_in[0];
    const float* ys      = (const float*)d_in[1];
    const float* scale   = (const float*)d_in[2];
    const float* mlp_w0  = (const float*)d_in[3];
    const float* mlp_b0  = (const float*)d_in[4];
    const float* mlp_w1  = (const float*)d_in[5];
    const float* mlp_b1  = (const float*)d_in[6];
    const float* mlp_w2  = (const float*)d_in[7];
    const float* mlp_b2  = (const float*)d_in[8];
    const float* gru_wih = (const float*)d_in[9];
    const float* gru_whh = (const float*)d_in[10];
    const float* gru_b   = (const float*)d_in[11];
    const float* gru_bn  = (const float*)d_in[12];
    const float* htl_w   = (const float*)d_in[13];
    const float* htl_b   = (const float*)d_in[14];
    const float* htb_w   = (const float*)d_in[15];
    const float* htb_b   = (const float*)d_in[16];
    const float* lti_w   = (const float*)d_in[17];
    const float* lti_b   = (const float*)d_in[18];
    const float* lth_w   = (const float*)d_in[19];
    const float* lth_b   = (const float*)d_in[20];

    static int attr_set = 0;
    if (!attr_set) {
        cudaFuncSetAttribute(solve_kernel,
                             cudaFuncAttributeMaxDynamicSharedMemorySize,
                             DYN_SMEM_BYTES);
        attr_set = 1;
    }

    prep_kernel<<<96, 256>>>(mlp_w0, mlp_w1, mlp_w2, gru_wih, gru_whh);
    solve_kernel<<<64, 512, DYN_SMEM_BYTES>>>(ts, ys, scale, mlp_b0, mlp_b1, mlp_b2,
                              gru_b, gru_bn, htl_w, htl_b, htb_w, htb_b,
                              lti_w, lti_b, lth_w, lth_b, (float*)d_out);
}

// round 6
// speedup vs baseline: 2.3501x; 2.1973x over previous
#include <cuda_runtime.h>
#include <cuda_bf16.h>

// Dims: B=64, T=64, D=32, H=128, W=256, L=64, K_SUB=2
typedef unsigned uint;

// ---------------- device scratch ----------------
__device__ float4 g_wihq[ 9 * 384];            // GRU input weights fp32 packed
__device__ float4 g_whhq[32 * 384];            // GRU hidden weights fp32 packed
// MLP weight tiles for ldmatrix: 16x16 bf16 tiles, row stride 48B (24 ushorts, 16 used)
__device__ unsigned short g_w0t[144 * 384];    // (256,144): 16 m-tiles x 9 k-tiles
__device__ unsigned short g_w2t[128 * 384];    // (128,256): 8 m-tiles x 16 k-tiles
// w1 A-fragments, per-thread: 16 k-tiles x 4 regs
__device__ uint4 g_w1f[512 * 16];

__device__ __forceinline__ uint pk_bf2(float a, float b) {
    uint lo = (uint)__bfloat16_as_ushort(__float2bfloat16_rn(a));
    uint hi = (uint)__bfloat16_as_ushort(__float2bfloat16_rn(b));
    return (hi << 16) | lo;
}

__global__ void prep_kernel(const float* __restrict__ w0, const float* __restrict__ w1,
                            const float* __restrict__ w2, const float* __restrict__ wih,
                            const float* __restrict__ whh)
{
    int i0 = blockIdx.x * blockDim.x + threadIdx.x;
    int stride = gridDim.x * blockDim.x;

    // w0 tiles: tile = mt*9+kt; element (r,c) at tile*384 + r*24 + c (c<16 valid)
    // K index 0 -> col0 (t_hi), 1..128 -> h, 129 -> col0 again (t_lo), else 0
    for (int idx = i0; idx < 144 * 384; idx += stride) {
        int tile = idx / 384, e = idx % 384, r = e / 24, c = e % 24;
        float v = 0.f;
        if (c < 16) {
            int mt = tile / 9, kt = tile % 9;
            int R = 16 * mt + r, K = 16 * kt + c;
            if (K < 129)      v = w0[R * 129 + K];
            else if (K == 129) v = w0[R * 129];
        }
        g_w0t[idx] = __bfloat16_as_ushort(__float2bfloat16_rn(v));
    }
    // w2 tiles: tile = mt*16+kt
    for (int idx = i0; idx < 128 * 384; idx += stride) {
        int tile = idx / 384, e = idx % 384, r = e / 24, c = e % 24;
        float v = 0.f;
        if (c < 16) {
            int mt = tile >> 4, kt = tile & 15;
            int R = 16 * mt + r, K = 16 * kt + c;
            v = w2[R * 256 + K];
        }
        g_w2t[idx] = __bfloat16_as_ushort(__float2bfloat16_rn(v));
    }
    // w1 fragments: idx = t*64 + kt*4 + i
    for (int idx = i0; idx < 512 * 64; idx += stride) {
        int t = idx >> 6, rem = idx & 63, kt = rem >> 2, i = rem & 3;
        int wid = t >> 5, lane = t & 31, g = lane >> 2, tig = lane & 3;
        int R = 16 * wid + g + ((i & 1) ? 8 : 0);
        int K = 16 * kt + 2 * tig + ((i & 2) ? 8 : 0);
        ((uint*)g_w1f)[idx] = pk_bf2(w1[R * 256 + K], w1[R * 256 + K + 1]);
    }
    // GRU fp32 packs
    for (int idx = i0; idx < 9 * 384; idx += stride) {
        int k4 = idx / 384, j = idx % 384, k = 4 * k4;
        float4 v;
        v.x = (k + 0 < 33) ? wih[j * 33 + k + 0] : 0.f;
        v.y = (k + 1 < 33) ? wih[j * 33 + k + 1] : 0.f;
        v.z = (k + 2 < 33) ? wih[j * 33 + k + 2] : 0.f;
        v.w = (k + 3 < 33) ? wih[j * 33 + k + 3] : 0.f;
        g_wihq[idx] = v;
    }
    for (int idx = i0; idx < 32 * 384; idx += stride) {
        int k4 = idx / 384, j = idx % 384, k = 4 * k4;
        g_whhq[idx] = make_float4(whh[j * 128 + k], whh[j * 128 + k + 1],
                                  whh[j * 128 + k + 2], whh[j * 128 + k + 3]);
    }
}

// ---------------- helpers ----------------
__device__ __forceinline__ uint smem_u32(const void* p) {
    return (uint)__cvta_generic_to_shared(p);
}
__device__ __forceinline__ void ldsm4(uint& r0, uint& r1, uint& r2, uint& r3, uint addr) {
    asm volatile("ldmatrix.sync.aligned.m8n8.x4.shared.b16 {%0,%1,%2,%3}, [%4];"
                 : "=r"(r0), "=r"(r1), "=r"(r2), "=r"(r3) : "r"(addr));
}
__device__ __forceinline__ void mma16816(float& d0, float& d1, float& d2, float& d3,
                                         uint a0, uint a1, uint a2, uint a3,
                                         uint b0, uint b1) {
    asm volatile("mma.sync.aligned.m16n8k16.row.col.f32.bf16.bf16.f32 "
                 "{%0,%1,%2,%3}, {%4,%5,%6,%7}, {%8,%9}, {%0,%1,%2,%3};"
                 : "+f"(d0), "+f"(d1), "+f"(d2), "+f"(d3)
                 : "r"(a0), "r"(a1), "r"(a2), "r"(a3), "r"(b0), "r"(b1));
}
__device__ __forceinline__ float tanh_fast(float x) {
    float y; asm("tanh.approx.f32 %0, %1;" : "=f"(y) : "f"(x)); return y;
}
__device__ __forceinline__ float softplus_fast(float x) {
    return fmaxf(x, 0.f) + __logf(1.f + __expf(-fabsf(x)));
}
__device__ __forceinline__ float sigmoid_fast(float x) { return 1.f / (1.f + __expf(-x)); }
__device__ __forceinline__ float sigmoidp(float x) { return 1.f / (1.f + expf(-x)); }

// dynamic smem: phase 1 = whh fp32 (196608B); phase 2 = w0 tiles (110592B) + w2 tiles (98304B)
#define DYN_SMEM_BYTES 208896
#define W2_SMEM_OFF    110592

__global__ void __launch_bounds__(512, 1)
solve_kernel(const float* __restrict__ ts, const float* __restrict__ ys,
             const float* __restrict__ scale,
             const float* __restrict__ mlp_b0, const float* __restrict__ mlp_b1,
             const float* __restrict__ mlp_b2,
             const float* __restrict__ gru_b, const float* __restrict__ gru_bn,
             const float* __restrict__ htl_w, const float* __restrict__ htl_b,
             const float* __restrict__ htb_w, const float* __restrict__ htb_b,
             const float* __restrict__ lti_w, const float* __restrict__ lti_b,
             const float* __restrict__ lth_w, const float* __restrict__ lth_b,
             float* __restrict__ out)
{
    const int b   = blockIdx.x;
    const int tid = threadIdx.x;
    const int lane = tid & 31, wid = tid >> 5;
    const int g = lane >> 2, tig = lane & 3;

    extern __shared__ __align__(16) char s_dyn[];

    __shared__ __align__(16) float s_xg[36];
    __shared__ __align__(16) float s_hid[128];
    __shared__ float s_ih[384], s_hh[384];
    __shared__ __align__(16) float s_y[136];
    __shared__ __align__(16) float s_tmp[136];
    __shared__ __align__(16) float s_k[6][136];
    __shared__ __align__(4) unsigned short s_xb[144];   // bf16 [t_hi, h(128), t_lo, 0...]
    __shared__ __align__(4) unsigned short s_a0b[256];  // bf16 activations
    __shared__ __align__(4) unsigned short s_a1b[256];
    __shared__ float s_p[256];                          // layer2 split-K partials
    __shared__ float s_z0[64];
    __shared__ float s_beta;

    const int OFF_H = 64 * 64 * 5;
    const int OFF_Z = OFF_H + 64 * 64 * 128;

    // ---- phase 1: whh into smem ----
    float4* s_whh = (float4*)s_dyn;
    for (int i = tid; i < 32 * 384; i += 512) s_whh[i] = g_whhq[i];

    const float gb  = (tid < 384) ? gru_b[tid]  : 0.f;
    const float gbn = (tid < 128) ? gru_bn[tid] : 0.f;

    if (tid < 128) s_hid[tid] = 0.f;
    if (tid >= 33 && tid < 36) s_xg[tid] = 0.f;
    __syncthreads();

    // ---------------- GRU over reversed sequence ----------------
    for (int step = 0; step < 64; ++step) {
        int r = 63 - step;
        if (tid == 0) s_xg[0] = ts[b * 64 + r];
        if (tid >= 1 && tid < 33) s_xg[tid] = ys[(b * 64 + r) * 32 + (tid - 1)];
        __syncthreads();

        if (tid < 384) {
            const float4* xg4 = (const float4*)s_xg;
            const float4* h4  = (const float4*)s_hid;
            int row = tid;
            float a0 = gb, a1 = 0.f;
            #pragma unroll
            for (int k = 0; k < 9; ++k) {
                float4 w = g_wihq[k * 384 + row];
                float4 x = xg4[k];
                a0 = fmaf(w.x, x.x, fmaf(w.z, x.z, a0));
                a1 = fmaf(w.y, x.y, fmaf(w.w, x.w, a1));
            }
            float c0 = 0.f, c1 = 0.f;
            #pragma unroll 8
            for (int k = 0; k < 32; ++k) {
                float4 w = s_whh[k * 384 + row];
                float4 x = h4[k];
                c0 = fmaf(w.x, x.x, fmaf(w.z, x.z, c0));
                c1 = fmaf(w.y, x.y, fmaf(w.w, x.w, c1));
            }
            s_ih[row] = a0 + a1;
            s_hh[row] = c0 + c1;
        }
        __syncthreads();
        if (tid < 128) {
            float rr = sigmoidp(s_ih[tid] + s_hh[tid]);
            float zz = sigmoidp(s_ih[128 + tid] + s_hh[128 + tid]);
            float nn = tanhf(s_ih[256 + tid] + rr * (s_hh[256 + tid] + gbn));
            s_hid[tid] = nn + zz * (s_hid[tid] - nn);
        }
        __syncthreads();
    }

    // ---------------- head ----------------
    if (tid < 64) {
        float acc = htl_b[tid];
        #pragma unroll 8
        for (int k = 0; k < 128; ++k) acc = fmaf(htl_w[tid * 128 + k], s_hid[k], acc);
        s_z0[tid] = acc;
        out[OFF_Z + b * 64 + tid] = acc;
    }
    __syncthreads();
    if (tid < 128) {
        float acc = lth_b[tid];
        #pragma unroll 8
        for (int k = 0; k < 64; ++k) acc = fmaf(lth_w[tid * 64 + k], s_z0[k], acc);
        s_y[5 + tid] = acc;
    }
    if (tid == 0) {
        float lg[5], mx = -1e30f;
        #pragma unroll
        for (int m = 0; m < 5; ++m) {
            float acc = lti_b[m];
            for (int k = 0; k < 64; ++k) acc = fmaf(lti_w[m * 64 + k], s_z0[k], acc);
            lg[m] = acc; mx = fmaxf(mx, acc);
        }
        float sum = 0.f;
        #pragma unroll
        for (int m = 0; m < 5; ++m) { float e = expf(lg[m] - mx); s_y[m] = e; sum += e; }
        #pragma unroll
        for (int m = 0; m < 5; ++m) s_y[m] /= sum;
    }
    __syncthreads();   // all done with s_whh + s_y ready

    // ---- phase 2: MLP weight tiles into smem ----
    {
        uint4* dst0 = (uint4*)s_dyn;
        const uint4* src0 = (const uint4*)g_w0t;
        for (int i = tid; i < 144 * 384 / 8; i += 512) dst0[i] = src0[i];
        uint4* dst2 = (uint4*)(s_dyn + W2_SMEM_OFF);
        const uint4* src2 = (const uint4*)g_w2t;
        for (int i = tid; i < 128 * 384 / 8; i += 512) dst2[i] = src2[i];
    }

    // w1 fragments into registers
    uint4 w1f[16];
    #pragma unroll
    for (int j = 0; j < 16; ++j) w1f[j] = g_w1f[tid * 16 + j];

    // per-thread constants
    const int rowg = 16 * wid + g;
    const float b0lo = mlp_b0[rowg], b0hi = mlp_b0[rowg + 8];
    const float b1lo = mlp_b1[rowg], b1hi = mlp_b1[rowg + 8];
    const float bias2r = (tid >= 5 && tid < 133) ? mlp_b2[tid - 5] : 0.f;
    const float scl = scale[0];

    float hw0 = 0.f, hw1 = 0.f, hw2 = 0.f, hw3 = 0.f, htbb = 0.f;
    if (wid == 15) {
        hw0 = htb_w[lane]; hw1 = htb_w[lane + 32];
        hw2 = htb_w[lane + 64]; hw3 = htb_w[lane + 96];
        htbb = htb_b[0];
    }

    const uint laneoff = (uint)((lane & 15) * 48 + (lane >> 4) * 16);
    const uint w0base = smem_u32(s_dyn) + (uint)(wid * 9 * 768) + laneoff;
    const uint w2base = smem_u32(s_dyn) + W2_SMEM_OFF
                      + (uint)(((wid & 7) * 16 + (wid >> 3) * 8) * 768) + laneoff;
    const int l2row = 16 * (wid & 7) + g;
    const int l2kh  = wid >> 3;

    // init xb from initial state; t=0
    if (tid < 128) s_xb[1 + tid] = __bfloat16_as_ushort(__float2bfloat16_rn(s_y[5 + tid]));
    if (tid == 256) { s_xb[0] = 0; s_xb[129] = 0; }
    if (tid >= 130 && tid < 144) s_xb[tid] = 0;
    __syncthreads();

    // ---------------- vf (xb + yv ready on entry; leaves s_p, s_beta ready) ----------------
    auto vf = [&](const float* yv) {
        // layer 0: ldsm tiles from smem, B from s_xb
        {
            const uint* xb32 = (const uint*)s_xb;
            float d0 = 0, d1 = 0, d2 = 0, d3 = 0;
            float e0 = 0, e1 = 0, e2 = 0, e3 = 0;
            #pragma unroll
            for (int kt = 0; kt < 9; ++kt) {
                uint a0, a1, a2, a3;
                ldsm4(a0, a1, a2, a3, w0base + (uint)(kt * 768));
                uint bb0 = 0, bb1 = 0;
                if (lane < 4) { bb0 = xb32[8 * kt + lane]; bb1 = xb32[8 * kt + 4 + lane]; }
                if (kt & 1) mma16816(e0, e1, e2, e3, a0, a1, a2, a3, bb0, bb1);
                else        mma16816(d0, d1, d2, d3, a0, a1, a2, a3, bb0, bb1);
            }
            d0 += e0; d2 += e2;
            if (tig == 0) {
                s_a0b[rowg]     = __bfloat16_as_ushort(__float2bfloat16_rn(softplus_fast(d0 + b0lo)));
                s_a0b[rowg + 8] = __bfloat16_as_ushort(__float2bfloat16_rn(softplus_fast(d2 + b0hi)));
            }
        }
        // beta on warp 15 (reads fp32 state)
        if (wid == 15) {
            float p = fmaf(hw0, yv[5 + lane],
                      fmaf(hw1, yv[37 + lane],
                      fmaf(hw2, yv[69 + lane], hw3 * yv[101 + lane])));
            #pragma unroll
            for (int o = 16; o > 0; o >>= 1) p += __shfl_xor_sync(0xffffffffu, p, o);
            if (lane == 0) s_beta = sigmoid_fast(0.01f * (p + htbb));
        }
        __syncthreads();

        // layer 1: A fragments in registers, B from s_a0b
        {
            const uint* xb32 = (const uint*)s_a0b;
            float d0 = 0, d1 = 0, d2 = 0, d3 = 0;
            float e0 = 0, e1 = 0, e2 = 0, e3 = 0;
            #pragma unroll
            for (int kt = 0; kt < 16; ++kt) {
                uint bb0 = 0, bb1 = 0;
                if (lane < 4) { bb0 = xb32[8 * kt + lane]; bb1 = xb32[8 * kt + 4 + lane]; }
                if (kt & 1) mma16816(e0, e1, e2, e3, w1f[kt].x, w1f[kt].y, w1f[kt].z, w1f[kt].w, bb0, bb1);
                else        mma16816(d0, d1, d2, d3, w1f[kt].x, w1f[kt].y, w1f[kt].z, w1f[kt].w, bb0, bb1);
            }
            d0 += e0; d2 += e2;
            if (tig == 0) {
                s_a1b[rowg]     = __bfloat16_as_ushort(__float2bfloat16_rn(softplus_fast(d0 + b1lo)));
                s_a1b[rowg + 8] = __bfloat16_as_ushort(__float2bfloat16_rn(softplus_fast(d2 + b1hi)));
            }
        }
        __syncthreads();

        // layer 2: split-K over warp pairs; partials into s_p
        {
            const uint* xb32 = (const uint*)s_a1b;
            float d0 = 0, d1 = 0, d2 = 0, d3 = 0;
            float e0 = 0, e1 = 0, e2 = 0, e3 = 0;
            #pragma unroll
            for (int j = 0; j < 8; ++j) {
                uint a0, a1, a2, a3;
                ldsm4(a0, a1, a2, a3, w2base + (uint)(j * 768));
                int kt = l2kh * 8 + j;
                uint bb0 = 0, bb1 = 0;
                if (lane < 4) { bb0 = xb32[8 * kt + lane]; bb1 = xb32[8 * kt + 4 + lane]; }
                if (j & 1) mma16816(e0, e1, e2, e3, a0, a1, a2, a3, bb0, bb1);
                else       mma16816(d0, d1, d2, d3, a0, a1, a2, a3, bb0, bb1);
            }
            d0 += e0; d2 += e2;
            if (tig == 0) {
                s_p[l2kh * 128 + l2row]     = d0;
                s_p[l2kh * 128 + l2row + 8] = d2;
            }
        }
        __syncthreads();
    };

    // new k for this thread (combine phase); yv = state the vf was evaluated at
    auto knew = [&](const float* yv) -> float {
        if (tid >= 5) {
            float z = s_p[tid - 5] + s_p[tid + 123] + bias2r;
            return scl * (0.1f * tanh_fast(1e-4f * z));
        }
        float S = yv[0], E = yv[1], I = yv[2], A = yv[3];
        float LL = 0.5f * I + A;
        float bSL = s_beta * S * LL;
        if (tid == 0) return -bSL;
        if (tid == 1) return bSL - 0.526f * E;
        if (tid == 2) return fmaf((float)(0.667 * 0.526), E, -(0.244f * I));
        if (tid == 3) return fmaf((float)((1.0 - 0.667) * 0.526), E, -(0.244f * A));
        return fmaf((float)(0.98 * 0.244), I, 0.244f * A);
    };

    auto set_t = [&](float tn) {
        unsigned short u = __bfloat16_as_ushort(__float2bfloat16_rn(tn));
        s_xb[0] = u;
        float thi = __uint_as_float(((uint)u) << 16);
        s_xb[129] = __bfloat16_as_ushort(__float2bfloat16_rn(tn - thi));
    };

    const float C2 = 0.161f, C3 = 0.327f, C4 = 0.9f;
    const float C5 = (float)0.9800255409045097;
    const float A21 = 0.161f;
    const float A31 = (float)-0.008480655492356989, A32 = (float)0.335480655492357;
    const float A41 = (float)2.8971530571054935,  A42 = (float)-6.359448489975075,
                A43 = (float)4.3622954328695815;
    const float A51 = (float)5.325864828439257,   A52 = (float)-11.748883564062828,
                A53 = (float)7.4955393428898365,  A54 = (float)-0.09249506636175525;
    const float A61 = (float)5.86145544294642,    A62 = (float)-12.92096931784711,
                A63 = (float)8.159367898576159,   A64 = (float)-0.071584973281401,
                A65 = (float)-0.028269050394068383;
    const float B1 = (float)0.09646076681806523, B2 = 0.01f,
                B3 = (float)0.4798896504144996,  B4 = (float)1.379008574103742,
                B5 = (float)-3.290069515436081,  B6 = (float)2.324710524099774;

    auto tsit5 = [&](float tt, float h, float t_after) {
        vf(s_y);
        if (tid < 133) {
            float k0 = knew(s_y); s_k[0][tid] = k0;
            float v = s_y[tid] + h * (A21 * k0);
            s_tmp[tid] = v;
            if (tid >= 5) s_xb[tid - 4] = __bfloat16_as_ushort(__float2bfloat16_rn(v));
        }
        if (tid == 256) set_t(tt + C2 * h);
        __syncthreads();

        vf(s_tmp);
        if (tid < 133) {
            float k1 = knew(s_tmp); s_k[1][tid] = k1;
            float v = s_y[tid] + h * (A31 * s_k[0][tid] + A32 * k1);
            s_tmp[tid] = v;
            if (tid >= 5) s_xb[tid - 4] = __bfloat16_as_ushort(__float2bfloat16_rn(v));
        }
        if (tid == 256) set_t(tt + C3 * h);
        __syncthreads();

        vf(s_tmp);
        if (tid < 133) {
            float k2 = knew(s_tmp); s_k[2][tid] = k2;
            float v = s_y[tid] + h * (A41 * s_k[0][tid] + A42 * s_k[1][tid] + A43 * k2);
            s_tmp[tid] = v;
            if (tid >= 5) s_xb[tid - 4] = __bfloat16_as_ushort(__float2bfloat16_rn(v));
        }
        if (tid == 256) set_t(tt + C4 * h);
        __syncthreads();

        vf(s_tmp);
        if (tid < 133) {
            float k3 = knew(s_tmp); s_k[3][tid] = k3;
            float v = s_y[tid] + h * (A51 * s_k[0][tid] + A52 * s_k[1][tid]
                                    + A53 * s_k[2][tid] + A54 * k3);
            s_tmp[tid] = v;
            if (tid >= 5) s_xb[tid - 4] = __bfloat16_as_ushort(__float2bfloat16_rn(v));
        }
        if (tid == 256) set_t(tt + C5 * h);
        __syncthreads();

        vf(s_tmp);
        if (tid < 133) {
            float k4 = knew(s_tmp); s_k[4][tid] = k4;
            float v = s_y[tid] + h * (A61 * s_k[0][tid] + A62 * s_k[1][tid]
                                    + A63 * s_k[2][tid] + A64 * s_k[3][tid] + A65 * k4);
            s_tmp[tid] = v;
            if (tid >= 5) s_xb[tid - 4] = __bfloat16_as_ushort(__float2bfloat16_rn(v));
        }
        if (tid == 256) set_t(tt + h);
        __syncthreads();

        vf(s_tmp);
        if (tid < 133) {
            float k5 = knew(s_tmp);
            float v = s_y[tid] + h * (B1 * s_k[0][tid] + B2 * s_k[1][tid]
                                    + B3 * s_k[2][tid] + B4 * s_k[3][tid]
                                    + B5 * s_k[4][tid] + B6 * k5);
            s_y[tid] = v;
            if (tid >= 5) s_xb[tid - 4] = __bfloat16_as_ushort(__float2bfloat16_rn(v));
        }
        if (tid == 256) set_t(t_after);
        __syncthreads();
    };

    float t0v = 0.f;
    for (int s = 0; s < 64; ++s) {
        float tn = ts[b * 64 + s];
        float dt = (tn - t0v) * 0.5f;    // K_SUB = 2
        tsit5(t0v,      dt, t0v + dt);
        tsit5(t0v + dt, dt, tn);
        t0v = tn;
        if (tid < 5)   out[(b * 64 + s) * 5 + tid] = s_y[tid];
        if (tid < 128) out[OFF_H + (b * 64 + s) * 128 + tid] = s_y[5 + tid];
    }
}

extern "C" void kernel_launch(void* const* d_in, const int* in_sizes, int n_in,
                              void* d_out, int out_size) {
    const float* ts      = (const float*)d_in[0];
    const float* ys      = (const float*)d_in[1];
    const float* scale   = (const float*)d_in[2];
    const float* mlp_w0  = (const float*)d_in[3];
    const float* mlp_b0  = (const float*)d_in[4];
    const float* mlp_w1  = (const float*)d_in[5];
    const float* mlp_b1  = (const float*)d_in[6];
    const float* mlp_w2  = (const float*)d_in[7];
    const float* mlp_b2  = (const float*)d_in[8];
    const float* gru_wih = (const float*)d_in[9];
    const float* gru_whh = (const float*)d_in[10];
    const float* gru_b   = (const float*)d_in[11];
    const float* gru_bn  = (const float*)d_in[12];
    const float* htl_w   = (const float*)d_in[13];
    const float* htl_b   = (const float*)d_in[14];
    const float* htb_w   = (const float*)d_in[15];
    const float* htb_b   = (const float*)d_in[16];
    const float* lti_w   = (const float*)d_in[17];
    const float* lti_b   = (const float*)d_in[18];
    const float* lth_w   = (const float*)d_in[19];
    const float* lth_b   = (const float*)d_in[20];

    static int attr_set = 0;
    if (!attr_set) {
        cudaFuncSetAttribute(solve_kernel,
                             cudaFuncAttributeMaxDynamicSharedMemorySize,
                             DYN_SMEM_BYTES);
        attr_set = 1;
    }

    prep_kernel<<<96, 256>>>(mlp_w0, mlp_w1, mlp_w2, gru_wih, gru_whh);
    solve_kernel<<<64, 512, DYN_SMEM_BYTES>>>(ts, ys, scale, mlp_b0, mlp_b1, mlp_b2,
                              gru_b, gru_bn, htl_w, htl_b, htb_w, htb_b,
                              lti_w, lti_b, lth_w, lth_b, (float*)d_out);
}